// round 1
// baseline (speedup 1.0000x reference)
#include <cuda_runtime.h>

#define BB 256
#define NN 128
#define CC 256

// Scratch for conv-gathered features (allowed: __device__ global, no cudaMalloc)
__device__ float g_Y[(size_t)BB * NN * CC];

// ---------------------------------------------------------------------------
// Kernel 1: per-batch min, bin quantization, and "virtual grid" conv-gather.
// One CTA per batch, 256 threads. y[i,c] = bias[c] + sum over neighbor pairs.
// ---------------------------------------------------------------------------
__global__ void __launch_bounds__(256) conv_gather_kernel(
    const float* __restrict__ x, const float* __restrict__ eta,
    const float* __restrict__ phi, const float* __restrict__ ck,
    const float* __restrict__ cb)
{
    int b = blockIdx.x;
    int t = threadIdx.x;
    int lane = t & 31;
    int w = t >> 5;

    __shared__ int   sge[NN];
    __shared__ int   sgp[NN];
    __shared__ float shK[9 * CC];
    __shared__ float shB[CC];
    __shared__ float warpmin[16];
    __shared__ float s_mine, s_minp;

    // stage conv kernel (3,3,1,C) and bias
    for (int i = t; i < 9 * CC; i += 256) shK[i] = ck[i];
    shB[t] = cb[t];

    // exact per-batch min of eta and phi over 128 values
    float ve = (t < NN) ? eta[b * NN + t] : 1e30f;
    float vp = (t < NN) ? phi[b * NN + t] : 1e30f;
    #pragma unroll
    for (int o = 16; o > 0; o >>= 1) {
        ve = fminf(ve, __shfl_xor_sync(0xffffffffu, ve, o));
        vp = fminf(vp, __shfl_xor_sync(0xffffffffu, vp, o));
    }
    if (lane == 0) { warpmin[w] = ve; warpmin[8 + w] = vp; }
    __syncthreads();
    if (t == 0) {
        float m = warpmin[0];
        #pragma unroll
        for (int i = 1; i < 8; i++) m = fminf(m, warpmin[i]);
        s_mine = m;
        float m2 = warpmin[8];
        #pragma unroll
        for (int i = 9; i < 16; i++) m2 = fminf(m2, warpmin[i]);
        s_minp = m2;
    }
    __syncthreads();

    if (t < NN) {
        // identical op sequence to jax: f32 sub, f32 div by 0.05f, trunc-to-int
        sge[t] = (int)((eta[b * NN + t] - s_mine) / 0.05f);
        sgp[t] = (int)((phi[b * NN + t] - s_minp) / 0.05f);
    }
    __syncthreads();

    const float* xb = x + (size_t)b * NN * CC;
    float* yb = g_Y + (size_t)b * NN * CC;
    int c0 = lane * 8;   // each lane owns 8 channels

    // each warp handles 16 particles
    for (int s = 0; s < 16; s++) {
        int i = w * 16 + s;
        int gi = sge[i], pi = sgp[i];

        float acc[8];
        #pragma unroll
        for (int u = 0; u < 8; u++) acc[u] = shB[c0 + u];

        for (int j = 0; j < NN; j++) {
            int dg = sge[j] - gi + 1;   // uniform across warp
            int dp = sgp[j] - pi + 1;
            if (((unsigned)dg <= 2u) && ((unsigned)dp <= 2u)) {
                int kk = dg * 3 + dp;
                const float4* xp = (const float4*)(xb + (size_t)j * CC + c0);
                float4 a0 = xp[0];
                float4 a1 = xp[1];
                const float4* kp = (const float4*)(shK + kk * CC + c0);
                float4 k0 = kp[0];
                float4 k1 = kp[1];
                acc[0] += k0.x * a0.x; acc[1] += k0.y * a0.y;
                acc[2] += k0.z * a0.z; acc[3] += k0.w * a0.w;
                acc[4] += k1.x * a1.x; acc[5] += k1.y * a1.y;
                acc[6] += k1.z * a1.z; acc[7] += k1.w * a1.w;
            }
        }
        float4* op = (float4*)(yb + (size_t)i * CC + c0);
        op[0] = make_float4(acc[0], acc[1], acc[2], acc[3]);
        op[1] = make_float4(acc[4], acc[5], acc[6], acc[7]);
    }
}

// ---------------------------------------------------------------------------
// Kernel 2: fused  out = x + LN(Y @ W + db) * gamma + beta
// One CTA per batch (128 rows x 256 cols). 256 threads as 16x16,
// each thread computes an 8x16 register tile. LN done in-CTA (full rows).
// ---------------------------------------------------------------------------
__global__ void __launch_bounds__(256, 1) gemm_ln_kernel(
    const float* __restrict__ W, const float* __restrict__ db,
    const float* __restrict__ gamma, const float* __restrict__ beta,
    const float* __restrict__ x, float* __restrict__ out)
{
    int b = blockIdx.x;
    int t = threadIdx.x;
    int tx = t & 15;   // output-column group (16 cols each)
    int ty = t >> 4;   // row group (8 rows each)

    __shared__ float shY[8][136];     // [k][row], padded
    __shared__ float shW[8][260];     // [k][col], padded
    __shared__ float redS[NN * 16];
    __shared__ float redQ[NN * 16];

    float acc[8][16];
    #pragma unroll
    for (int r = 0; r < 8; r++)
        #pragma unroll
        for (int c = 0; c < 16; c++) acc[r][c] = 0.f;

    const float* Yb = g_Y + (size_t)b * NN * CC;

    for (int kb = 0; kb < CC; kb += 8) {
        __syncthreads();
        // stage Y tile: 128 rows x 8 k (transposed into smem)
        #pragma unroll
        for (int p = 0; p < 4; p++) {
            int idx = p * 256 + t;
            int row = idx >> 3;
            int kk  = idx & 7;
            shY[kk][row] = Yb[(size_t)row * CC + kb + kk];
        }
        // stage W tile: 8 k-rows x 256 cols
        {
            int r = t >> 5;
            int c = (t & 31) * 8;
            const float4* wp = (const float4*)(W + (size_t)(kb + r) * CC + c);
            float4 w0 = wp[0];
            float4 w1 = wp[1];
            *(float4*)&shW[r][c]     = w0;
            *(float4*)&shW[r][c + 4] = w1;
        }
        __syncthreads();

        #pragma unroll
        for (int kk = 0; kk < 8; kk++) {
            float yf[8], wf[16];
            *(float4*)&yf[0] = *(const float4*)&shY[kk][ty * 8];
            *(float4*)&yf[4] = *(const float4*)&shY[kk][ty * 8 + 4];
            #pragma unroll
            for (int u = 0; u < 4; u++)
                *(float4*)&wf[u * 4] = *(const float4*)&shW[kk][tx * 16 + u * 4];
            #pragma unroll
            for (int r = 0; r < 8; r++)
                #pragma unroll
                for (int c = 0; c < 16; c++)
                    acc[r][c] += yf[r] * wf[c];
        }
    }

    // epilogue params for this thread's 16 columns
    float gb[16], bbv[16], dbv[16];
    #pragma unroll
    for (int u = 0; u < 4; u++) {
        *(float4*)&dbv[u * 4] = *(const float4*)(db    + tx * 16 + u * 4);
        *(float4*)&gb[u * 4]  = *(const float4*)(gamma + tx * 16 + u * 4);
        *(float4*)&bbv[u * 4] = *(const float4*)(beta  + tx * 16 + u * 4);
    }

    // per-row partial sums for LayerNorm
    #pragma unroll
    for (int r = 0; r < 8; r++) {
        float s = 0.f, q = 0.f;
        #pragma unroll
        for (int c = 0; c < 16; c++) {
            float v = acc[r][c] + dbv[c];
            acc[r][c] = v;
            s += v;
            q += v * v;
        }
        int row = ty * 8 + r;
        redS[row * 16 + tx] = s;
        redQ[row * 16 + tx] = q;
    }
    __syncthreads();

    #pragma unroll
    for (int r = 0; r < 8; r++) {
        int row = ty * 8 + r;
        float s = 0.f, q = 0.f;
        #pragma unroll
        for (int c = 0; c < 16; c++) {
            s += redS[row * 16 + c];
            q += redQ[row * 16 + c];
        }
        float mean = s * (1.0f / 256.0f);
        float var  = fmaf(-mean, mean, q * (1.0f / 256.0f));
        float inv  = rsqrtf(var + 1e-6f);

        const float* xr = x   + ((size_t)b * NN + row) * CC + tx * 16;
        float* orow     = out + ((size_t)b * NN + row) * CC + tx * 16;
        #pragma unroll
        for (int u = 0; u < 4; u++) {
            float4 xv = *(const float4*)(xr + u * 4);
            float4 o;
            o.x = (acc[r][u * 4 + 0] - mean) * inv * gb[u * 4 + 0] + bbv[u * 4 + 0] + xv.x;
            o.y = (acc[r][u * 4 + 1] - mean) * inv * gb[u * 4 + 1] + bbv[u * 4 + 1] + xv.y;
            o.z = (acc[r][u * 4 + 2] - mean) * inv * gb[u * 4 + 2] + bbv[u * 4 + 2] + xv.z;
            o.w = (acc[r][u * 4 + 3] - mean) * inv * gb[u * 4 + 3] + bbv[u * 4 + 3] + xv.w;
            *(float4*)(orow + u * 4) = o;
        }
    }
}

extern "C" void kernel_launch(void* const* d_in, const int* in_sizes, int n_in,
                              void* d_out, int out_size) {
    const float* x   = (const float*)d_in[0];
    const float* eta = (const float*)d_in[1];
    const float* phi = (const float*)d_in[2];
    const float* ck  = (const float*)d_in[3];
    const float* cb  = (const float*)d_in[4];
    const float* dw  = (const float*)d_in[5];
    const float* db  = (const float*)d_in[6];
    const float* gm  = (const float*)d_in[7];
    const float* bt  = (const float*)d_in[8];
    float* out = (float*)d_out;

    conv_gather_kernel<<<BB, 256>>>(x, eta, phi, ck, cb);
    gemm_ln_kernel<<<BB, 256>>>(dw, db, gm, bt, x, out);
}

// round 3
// speedup vs baseline: 3.9384x; 3.9384x over previous
#include <cuda_runtime.h>
#include <cuda_bf16.h>
#include <cstdint>

#define BB 256
#define NN 128
#define CC 256

// Global images:
// A (per batch): [8 kchunks][128 rows][32 bf16] hi/lo  -> 64KB/batch each
// B = W^T:       [8 kchunks][256 rows][32 bf16] hi/lo  -> 128KB each
__device__ __align__(16) unsigned char g_Ahi[(size_t)BB * 65536];
__device__ __align__(16) unsigned char g_Alo[(size_t)BB * 65536];
__device__ __align__(16) unsigned char g_Bhi[131072];
__device__ __align__(16) unsigned char g_Blo[131072];

__device__ __forceinline__ uint32_t smem_u32(const void* p) {
    uint32_t a;
    asm("{ .reg .u64 t; cvta.to.shared.u64 t, %1; cvt.u32.u64 %0, t; }"
        : "=r"(a) : "l"(p));
    return a;
}

__device__ __forceinline__ void ldsm_x4(uint32_t& r0, uint32_t& r1, uint32_t& r2,
                                        uint32_t& r3, uint32_t addr) {
    asm volatile("ldmatrix.sync.aligned.m8n8.x4.shared.b16 {%0,%1,%2,%3}, [%4];"
                 : "=r"(r0), "=r"(r1), "=r"(r2), "=r"(r3) : "r"(addr));
}

__device__ __forceinline__ void mma16816(float* d, const uint32_t* a, const uint32_t* b) {
    asm volatile(
        "mma.sync.aligned.m16n8k16.row.col.f32.bf16.bf16.f32 "
        "{%0,%1,%2,%3}, {%4,%5,%6,%7}, {%8,%9}, {%0,%1,%2,%3};"
        : "+f"(d[0]), "+f"(d[1]), "+f"(d[2]), "+f"(d[3])
        : "r"(a[0]), "r"(a[1]), "r"(a[2]), "r"(a[3]), "r"(b[0]), "r"(b[1]));
}

__device__ __forceinline__ void cp16(uint32_t dst, const void* src) {
    asm volatile("cp.async.cg.shared.global [%0], [%1], 16;" :: "r"(dst), "l"(src));
}

__device__ __forceinline__ void split_pack(const float* a, uint32_t* hi, uint32_t* lo) {
    #pragma unroll
    for (int u = 0; u < 4; u++) {
        float a0 = a[2 * u], a1 = a[2 * u + 1];
        __nv_bfloat16 h0 = __float2bfloat16(a0);
        __nv_bfloat16 h1 = __float2bfloat16(a1);
        __nv_bfloat16 l0 = __float2bfloat16(a0 - __bfloat162float(h0));
        __nv_bfloat16 l1 = __float2bfloat16(a1 - __bfloat162float(h1));
        hi[u] = ((uint32_t)__bfloat16_as_ushort(h1) << 16) | __bfloat16_as_ushort(h0);
        lo[u] = ((uint32_t)__bfloat16_as_ushort(l1) << 16) | __bfloat16_as_ushort(l0);
    }
}

// ---------------------------------------------------------------------------
// Kernel 0: W^T hi/lo images. B[n][k] = W[k][n]. 32 CTAs x 256 threads.
// ---------------------------------------------------------------------------
__global__ void __launch_bounds__(256) prep_w_kernel(const float* __restrict__ W) {
    int e = blockIdx.x * 256 + threadIdx.x;   // 8192
    int n = e >> 5;
    int k0 = (e & 31) * 8;
    float a[8];
    #pragma unroll
    for (int u = 0; u < 8; u++) a[u] = W[(size_t)(k0 + u) * CC + n];
    uint32_t hi[4], lo[4];
    split_pack(a, hi, lo);
    size_t off = (size_t)(k0 >> 5) * 16384 + n * 64 + (k0 & 31) * 2;
    *(uint4*)(g_Bhi + off) = make_uint4(hi[0], hi[1], hi[2], hi[3]);
    *(uint4*)(g_Blo + off) = make_uint4(lo[0], lo[1], lo[2], lo[3]);
}

// ---------------------------------------------------------------------------
// Kernel 1: bins + neighbor lists + sparse conv-gather -> bf16 hi/lo images.
// ---------------------------------------------------------------------------
__global__ void __launch_bounds__(256) conv_gather_kernel(
    const float* __restrict__ x, const float* __restrict__ eta,
    const float* __restrict__ phi, const float* __restrict__ ck,
    const float* __restrict__ cb)
{
    int b = blockIdx.x;
    int t = threadIdx.x;
    int lane = t & 31;
    int w = t >> 5;

    __shared__ int sge[NN];
    __shared__ int sgp[NN];
    __shared__ int scnt[NN];
    __shared__ unsigned short nb[NN][NN];
    __shared__ float shK[9 * CC];
    __shared__ float shB[CC];
    __shared__ float warpmin[16];
    __shared__ float s_mine, s_minp;

    for (int i = t; i < 9 * CC; i += 256) shK[i] = ck[i];
    shB[t] = cb[t];

    float ve = (t < NN) ? eta[b * NN + t] : 1e30f;
    float vp = (t < NN) ? phi[b * NN + t] : 1e30f;
    #pragma unroll
    for (int o = 16; o > 0; o >>= 1) {
        ve = fminf(ve, __shfl_xor_sync(0xffffffffu, ve, o));
        vp = fminf(vp, __shfl_xor_sync(0xffffffffu, vp, o));
    }
    if (lane == 0) { warpmin[w] = ve; warpmin[8 + w] = vp; }
    __syncthreads();
    if (t == 0) {
        float m = warpmin[0];
        #pragma unroll
        for (int i = 1; i < 8; i++) m = fminf(m, warpmin[i]);
        s_mine = m;
        float m2 = warpmin[8];
        #pragma unroll
        for (int i = 9; i < 16; i++) m2 = fminf(m2, warpmin[i]);
        s_minp = m2;
    }
    __syncthreads();

    if (t < NN) {
        sge[t] = (int)((eta[b * NN + t] - s_mine) / 0.05f);
        sgp[t] = (int)((phi[b * NN + t] - s_minp) / 0.05f);
    }
    __syncthreads();

    if (t < NN) {
        int gi = sge[t], pi = sgp[t];
        int cnt = 0;
        for (int j = 0; j < NN; j++) {
            unsigned dg = (unsigned)(sge[j] - gi + 1);
            unsigned dp = (unsigned)(sgp[j] - pi + 1);
            if (dg <= 2u && dp <= 2u)
                nb[t][cnt++] = (unsigned short)(j | ((dg * 3 + dp) << 8));
        }
        scnt[t] = cnt;
    }
    __syncthreads();

    const float* xb = x + (size_t)b * NN * CC;
    int c0 = lane * 8;
    size_t abase = (size_t)b * 65536 + (size_t)(c0 >> 5) * 8192 + (c0 & 31) * 2;

    for (int s = 0; s < 16; s++) {
        int i = w * 16 + s;
        float acc[8];
        #pragma unroll
        for (int u = 0; u < 8; u++) acc[u] = shB[c0 + u];

        int cnt = scnt[i];
        for (int e = 0; e < cnt; e++) {
            int pk = nb[i][e];
            int j = pk & 0xFF;
            int kk = pk >> 8;
            const float4* xp = (const float4*)(xb + (size_t)j * CC + c0);
            float4 a0 = xp[0];
            float4 a1 = xp[1];
            const float4* kp = (const float4*)(shK + kk * CC + c0);
            float4 k0 = kp[0];
            float4 k1 = kp[1];
            acc[0] += k0.x * a0.x; acc[1] += k0.y * a0.y;
            acc[2] += k0.z * a0.z; acc[3] += k0.w * a0.w;
            acc[4] += k1.x * a1.x; acc[5] += k1.y * a1.y;
            acc[6] += k1.z * a1.z; acc[7] += k1.w * a1.w;
        }

        uint32_t hi[4], lo[4];
        split_pack(acc, hi, lo);
        *(uint4*)(g_Ahi + abase + (size_t)i * 64) = make_uint4(hi[0], hi[1], hi[2], hi[3]);
        *(uint4*)(g_Alo + abase + (size_t)i * 64) = make_uint4(lo[0], lo[1], lo[2], lo[3]);
    }
}

// ---------------------------------------------------------------------------
// Kernel 2: HMMA split-bf16 GEMM (M=128, N=256, K=256) + bias + LN + residual.
// One CTA per batch, 512 threads (16 warps). Warp tile 64x32.
// SMEM rows padded to 80B -> conflict-free ldmatrix.
// ---------------------------------------------------------------------------
#define ROWPAD 80
#define ST_AHI 0
#define ST_ALO 10240
#define ST_BHI 20480
#define ST_BLO 40960
#define STAGE  61440
#define SPAR   122880   // db[256], gamma[256], beta[256]
#define SRED   125952   // redS[128*8], redQ[128*8]
#define SMI    134144   // float2 per row
#define SMEM2  135168

__global__ void __launch_bounds__(512, 1) gemm_ln_kernel(
    const float* __restrict__ db, const float* __restrict__ gamma,
    const float* __restrict__ beta, const float* __restrict__ x,
    float* __restrict__ out)
{
    extern __shared__ char smem[];
    uint32_t sb = smem_u32(smem);
    int b = blockIdx.x;
    int t = threadIdx.x;
    int lane = t & 31;
    int w = t >> 5;
    int mw = w & 1;          // M half (0/1): rows mw*64..+63
    int nw = w >> 1;         // N slice (0..7): cols nw*32..+31

    const unsigned char* gAh = g_Ahi + (size_t)b * 65536;
    const unsigned char* gAl = g_Alo + (size_t)b * 65536;

    // stage copy helper (chunk kc -> stage buffer s)
    auto copy_stage = [&](int s, int kc) {
        uint32_t st = sb + s * STAGE;
        // A: 512 uint4 per image
        {
            int row = t >> 2, seg = t & 3;
            uint32_t d = st + row * ROWPAD + seg * 16;
            cp16(d + ST_AHI, gAh + (size_t)kc * 8192 + t * 16);
            cp16(d + ST_ALO, gAl + (size_t)kc * 8192 + t * 16);
        }
        // B: 1024 uint4 per image
        #pragma unroll
        for (int p = 0; p < 2; p++) {
            int idx = t + p * 512;
            int row = idx >> 2, seg = idx & 3;
            uint32_t d = st + row * ROWPAD + seg * 16;
            cp16(d + ST_BHI, g_Bhi + (size_t)kc * 16384 + idx * 16);
            cp16(d + ST_BLO, g_Blo + (size_t)kc * 16384 + idx * 16);
        }
    };

    copy_stage(0, 0);
    asm volatile("cp.async.commit_group;" ::: "memory");

    // stage params meanwhile
    if (t < 256) {
        ((float*)(smem + SPAR))[t]        = db[t];
        ((float*)(smem + SPAR + 1024))[t] = gamma[t];
        ((float*)(smem + SPAR + 2048))[t] = beta[t];
    }

    float acc[4][4][4];
    #pragma unroll
    for (int i = 0; i < 4; i++)
        #pragma unroll
        for (int j = 0; j < 4; j++)
            #pragma unroll
            for (int d = 0; d < 4; d++) acc[i][j][d] = 0.f;

    // precomputed ldmatrix row offsets for this lane
    int aRow = (lane & 7) + ((lane >> 3) & 1) * 8;         // + mt*16 + mw*64
    uint32_t aKb = (uint32_t)((lane >> 4) * 16);            // + ks*32
    int bRow = (lane & 7) + ((lane >= 16) ? 8 : 0);         // + np*16 + nw*32
    uint32_t bKb = (uint32_t)(((lane >> 3) & 1) * 16);      // + ks*32

    for (int kc = 0; kc < 8; kc++) {
        asm volatile("cp.async.wait_group 0;" ::: "memory");
        __syncthreads();
        if (kc < 7) {
            copy_stage((kc + 1) & 1, kc + 1);
            asm volatile("cp.async.commit_group;" ::: "memory");
        }

        uint32_t st = sb + (kc & 1) * STAGE;
        uint32_t sAhi = st + ST_AHI + (mw * 64 + aRow) * ROWPAD + aKb;
        uint32_t sAlo = st + ST_ALO + (mw * 64 + aRow) * ROWPAD + aKb;
        uint32_t sBhi = st + ST_BHI + (nw * 32 + bRow) * ROWPAD + bKb;
        uint32_t sBlo = st + ST_BLO + (nw * 32 + bRow) * ROWPAD + bKb;

        #pragma unroll
        for (int ks = 0; ks < 2; ks++) {
            uint32_t ahi[4][4], alo[4][4], bhi[4][2], blo[4][2];
            #pragma unroll
            for (int mt = 0; mt < 4; mt++) {
                uint32_t a = sAhi + mt * (16 * ROWPAD) + ks * 32;
                ldsm_x4(ahi[mt][0], ahi[mt][1], ahi[mt][2], ahi[mt][3], a);
                uint32_t al = sAlo + mt * (16 * ROWPAD) + ks * 32;
                ldsm_x4(alo[mt][0], alo[mt][1], alo[mt][2], alo[mt][3], al);
            }
            #pragma unroll
            for (int np = 0; np < 2; np++) {
                uint32_t r0, r1, r2, r3;
                ldsm_x4(r0, r1, r2, r3, sBhi + np * (16 * ROWPAD) + ks * 32);
                bhi[2 * np][0] = r0; bhi[2 * np][1] = r1;
                bhi[2 * np + 1][0] = r2; bhi[2 * np + 1][1] = r3;
                ldsm_x4(r0, r1, r2, r3, sBlo + np * (16 * ROWPAD) + ks * 32);
                blo[2 * np][0] = r0; blo[2 * np][1] = r1;
                blo[2 * np + 1][0] = r2; blo[2 * np + 1][1] = r3;
            }
            #pragma unroll
            for (int mt = 0; mt < 4; mt++)
                #pragma unroll
                for (int nt = 0; nt < 4; nt++) {
                    mma16816(acc[mt][nt], ahi[mt], bhi[nt]);
                    mma16816(acc[mt][nt], alo[mt], bhi[nt]);
                    mma16816(acc[mt][nt], ahi[mt], blo[nt]);
                }
        }
    }

    // ---------------- epilogue: bias + LN + residual ----------------
    const float* s_db = (const float*)(smem + SPAR);
    const float* s_g  = (const float*)(smem + SPAR + 1024);
    const float* s_bt = (const float*)(smem + SPAR + 2048);
    float* redS = (float*)(smem + SRED);
    float* redQ = (float*)(smem + SRED + 4096);
    float2* smi = (float2*)(smem + SMI);

    int qr = lane >> 2, qc = lane & 3;
    int MW = mw * 64, NW = nw * 32;

    float S[4][2], Q[4][2];
    #pragma unroll
    for (int mt = 0; mt < 4; mt++) {
        S[mt][0] = S[mt][1] = 0.f;
        Q[mt][0] = Q[mt][1] = 0.f;
    }
    #pragma unroll
    for (int mt = 0; mt < 4; mt++)
        #pragma unroll
        for (int nt = 0; nt < 4; nt++)
            #pragma unroll
            for (int d = 0; d < 4; d++) {
                int col = NW + nt * 8 + qc * 2 + (d & 1);
                float v = acc[mt][nt][d] + s_db[col];
                acc[mt][nt][d] = v;
                S[mt][d >> 1] += v;
                Q[mt][d >> 1] += v * v;
            }
    // reduce across the quad (lanes sharing qr)
    #pragma unroll
    for (int mt = 0; mt < 4; mt++)
        #pragma unroll
        for (int h = 0; h < 2; h++) {
            #pragma unroll
            for (int off = 1; off <= 2; off <<= 1) {
                S[mt][h] += __shfl_xor_sync(0xffffffffu, S[mt][h], off);
                Q[mt][h] += __shfl_xor_sync(0xffffffffu, Q[mt][h], off);
            }
        }
    if (qc == 0) {
        #pragma unroll
        for (int mt = 0; mt < 4; mt++)
            #pragma unroll
            for (int h = 0; h < 2; h++) {
                int row = MW + mt * 16 + qr + h * 8;
                redS[row * 8 + nw] = S[mt][h];
                redQ[row * 8 + nw] = Q[mt][h];
            }
    }
    __syncthreads();

    if (t < 128) {
        float s = 0.f, q = 0.f;
        #pragma unroll
        for (int k = 0; k < 8; k++) {
            s += redS[t * 8 + k];
            q += redQ[t * 8 + k];
        }
        float mean = s * (1.0f / 256.0f);
        float var = fmaf(-mean, mean, q * (1.0f / 256.0f));
        smi[t] = make_float2(mean, rsqrtf(var + 1e-6f));
    }
    __syncthreads();

    #pragma unroll
    for (int mt = 0; mt < 4; mt++)
        #pragma unroll
        for (int h = 0; h < 2; h++) {
            int row = MW + mt * 16 + qr + h * 8;
            float2 mv = smi[row];
            size_t rb = ((size_t)b * NN + row) * CC;
            #pragma unroll
            for (int nt = 0; nt < 4; nt++) {
                int col = NW + nt * 8 + qc * 2;
                float2 xv = *(const float2*)(x + rb + col);
                float v0 = (acc[mt][nt][h * 2]     - mv.x) * mv.y * s_g[col]     + s_bt[col]     + xv.x;
                float v1 = (acc[mt][nt][h * 2 + 1] - mv.x) * mv.y * s_g[col + 1] + s_bt[col + 1] + xv.y;
                *(float2*)(out + rb + col) = make_float2(v0, v1);
            }
        }
}

extern "C" void kernel_launch(void* const* d_in, const int* in_sizes, int n_in,
                              void* d_out, int out_size) {
    const float* x   = (const float*)d_in[0];
    const float* eta = (const float*)d_in[1];
    const float* phi = (const float*)d_in[2];
    const float* ck  = (const float*)d_in[3];
    const float* cb  = (const float*)d_in[4];
    const float* dw  = (const float*)d_in[5];
    const float* db  = (const float*)d_in[6];
    const float* gm  = (const float*)d_in[7];
    const float* bt  = (const float*)d_in[8];
    float* out = (float*)d_out;

    cudaFuncSetAttribute(gemm_ln_kernel,
                         cudaFuncAttributeMaxDynamicSharedMemorySize, SMEM2);

    prep_w_kernel<<<32, 256>>>(dw);
    conv_gather_kernel<<<BB, 256>>>(x, eta, phi, ck, cb);
    gemm_ln_kernel<<<BB, 512, SMEM2>>>(db, gm, bt, x, out);
}

// round 4
// speedup vs baseline: 4.2587x; 1.0813x over previous
#include <cuda_runtime.h>
#include <cuda_bf16.h>
#include <cstdint>

#define BB 256
#define NN 128
#define CC 256

// B = W^T hi/lo images: [8 kchunks][256 rows][32 bf16] -> 128KB each
__device__ __align__(16) unsigned char g_Bhi[131072];
__device__ __align__(16) unsigned char g_Blo[131072];

__device__ __forceinline__ uint32_t smem_u32(const void* p) {
    uint32_t a;
    asm("{ .reg .u64 t; cvta.to.shared.u64 t, %1; cvt.u32.u64 %0, t; }"
        : "=r"(a) : "l"(p));
    return a;
}

__device__ __forceinline__ void ldsm_x4(uint32_t& r0, uint32_t& r1, uint32_t& r2,
                                        uint32_t& r3, uint32_t addr) {
    asm volatile("ldmatrix.sync.aligned.m8n8.x4.shared.b16 {%0,%1,%2,%3}, [%4];"
                 : "=r"(r0), "=r"(r1), "=r"(r2), "=r"(r3) : "r"(addr));
}

__device__ __forceinline__ void mma16816(float* d, const uint32_t* a, const uint32_t* b) {
    asm volatile(
        "mma.sync.aligned.m16n8k16.row.col.f32.bf16.bf16.f32 "
        "{%0,%1,%2,%3}, {%4,%5,%6,%7}, {%8,%9}, {%0,%1,%2,%3};"
        : "+f"(d[0]), "+f"(d[1]), "+f"(d[2]), "+f"(d[3])
        : "r"(a[0]), "r"(a[1]), "r"(a[2]), "r"(a[3]), "r"(b[0]), "r"(b[1]));
}

__device__ __forceinline__ void cp16(uint32_t dst, const void* src) {
    asm volatile("cp.async.cg.shared.global [%0], [%1], 16;" :: "r"(dst), "l"(src));
}

__device__ __forceinline__ void split_pack(const float* a, uint32_t* hi, uint32_t* lo) {
    #pragma unroll
    for (int u = 0; u < 4; u++) {
        float a0 = a[2 * u], a1 = a[2 * u + 1];
        __nv_bfloat16 h0 = __float2bfloat16(a0);
        __nv_bfloat16 h1 = __float2bfloat16(a1);
        __nv_bfloat16 l0 = __float2bfloat16(a0 - __bfloat162float(h0));
        __nv_bfloat16 l1 = __float2bfloat16(a1 - __bfloat162float(h1));
        hi[u] = ((uint32_t)__bfloat16_as_ushort(h1) << 16) | __bfloat16_as_ushort(h0);
        lo[u] = ((uint32_t)__bfloat16_as_ushort(l1) << 16) | __bfloat16_as_ushort(l0);
    }
}

// ---------------------------------------------------------------------------
// Kernel 0: W^T hi/lo images (coalesced). warp w: k0=(w>>3)*8, n=(w&7)*32+lane.
// ---------------------------------------------------------------------------
__global__ void __launch_bounds__(256) prep_w_kernel(const float* __restrict__ W) {
    int e = blockIdx.x * 256 + threadIdx.x;   // 8192
    int lane = e & 31;
    int w = e >> 5;                            // 256 warps
    int n = (w & 7) * 32 + lane;
    int k0 = (w >> 3) * 8;
    float a[8];
    #pragma unroll
    for (int u = 0; u < 8; u++) a[u] = W[(size_t)(k0 + u) * CC + n];  // coalesced
    uint32_t hi[4], lo[4];
    split_pack(a, hi, lo);
    size_t off = (size_t)(k0 >> 5) * 16384 + n * 64 + (k0 & 31) * 2;
    *(uint4*)(g_Bhi + off) = make_uint4(hi[0], hi[1], hi[2], hi[3]);
    *(uint4*)(g_Blo + off) = make_uint4(lo[0], lo[1], lo[2], lo[3]);
}

// ---------------------------------------------------------------------------
// Fused kernel: bins + neighbor conv -> SMEM A (bf16 hi/lo, XOR swizzle),
// then HMMA split-bf16 GEMM + bias + LN + residual. 1 CTA/batch, 512 threads.
//
// A layout: [8 chunks 16KB][128 rows 128B]; row = hi quads 0-3 | lo quads 4-7,
//           quad index XOR (row&7) -> conflict-free ldmatrix.
// B stage layout: rows padded to 80B (conflict-free ldmatrix), double buffered.
// ---------------------------------------------------------------------------
#define ROWPAD 80
#define SA      0               // 131072
#define SB      131072          // 2 stages x 40960
#define ST_BLO  20480
#define STAGE   40960
#define SNB     172032          // nb ushort[128][128] = 32768 (aliases B stage 1)
#define SPAR    212992          // db, gamma, beta (3 x 1024)
#define SRED    216064          // redS 4096 + redQ 4096 (aliased by shK during conv)
#define SMI     224256          // float2[128]
#define SMISC   225280          // shB 1024 | sge 512 | sgp 512 | scnt 512 | wmin 64 | mins 8
#define SMEMT   228352

__global__ void __launch_bounds__(512, 1) fused_kernel(
    const float* __restrict__ x, const float* __restrict__ eta,
    const float* __restrict__ phi, const float* __restrict__ ck,
    const float* __restrict__ cb, const float* __restrict__ db,
    const float* __restrict__ gamma, const float* __restrict__ beta,
    float* __restrict__ out)
{
    extern __shared__ char smem[];
    uint32_t sb = smem_u32(smem);
    int b = blockIdx.x;
    int t = threadIdx.x;
    int lane = t & 31;
    int w = t >> 5;

    // ---- B chunk 0 prefetch (overlaps conv phase) ----
    auto copy_stage = [&](int s, int kc) {
        uint32_t st = sb + SB + s * STAGE;
        #pragma unroll
        for (int p = 0; p < 2; p++) {
            int idx = t + p * 512;
            int row = idx >> 2, seg = idx & 3;
            uint32_t d = st + row * ROWPAD + seg * 16;
            cp16(d, g_Bhi + (size_t)kc * 16384 + idx * 16);
            cp16(d + ST_BLO, g_Blo + (size_t)kc * 16384 + idx * 16);
        }
    };
    copy_stage(0, 0);
    asm volatile("cp.async.commit_group;" ::: "memory");

    // params
    if (t < 256) {
        ((float*)(smem + SPAR))[t]        = db[t];
        ((float*)(smem + SPAR + 1024))[t] = gamma[t];
        ((float*)(smem + SPAR + 2048))[t] = beta[t];
    }

    // ---- conv-phase shared views ----
    float* shB   = (float*)(smem + SMISC);
    int*   sge   = (int*)(smem + SMISC + 1024);
    int*   sgp   = (int*)(smem + SMISC + 1536);
    int*   scnt  = (int*)(smem + SMISC + 2048);
    float* wmin  = (float*)(smem + SMISC + 2560);
    float* mins  = (float*)(smem + SMISC + 2624);
    float* shK   = (float*)(smem + SRED);          // 9216B, aliases redS/redQ/SMI
    unsigned short (*nb)[NN] = (unsigned short (*)[NN])(smem + SNB);

    // ---- per-batch min ----
    float ve = (t < NN) ? eta[b * NN + t] : 1e30f;
    float vp = (t < NN) ? phi[b * NN + t] : 1e30f;
    #pragma unroll
    for (int o = 16; o > 0; o >>= 1) {
        ve = fminf(ve, __shfl_xor_sync(0xffffffffu, ve, o));
        vp = fminf(vp, __shfl_xor_sync(0xffffffffu, vp, o));
    }
    if (lane == 0 && w < 4) { wmin[w] = ve; wmin[4 + w] = vp; }
    __syncthreads();
    if (t == 0) {
        mins[0] = fminf(fminf(wmin[0], wmin[1]), fminf(wmin[2], wmin[3]));
        mins[1] = fminf(fminf(wmin[4], wmin[5]), fminf(wmin[6], wmin[7]));
    }
    __syncthreads();
    if (t < NN) {
        sge[t] = (int)((eta[b * NN + t] - mins[0]) / 0.05f);
        sgp[t] = (int)((phi[b * NN + t] - mins[1]) / 0.05f);
    }
    __syncthreads();

    // ---- neighbor lists (t<128) while others stage conv weights ----
    if (t < NN) {
        int gi = sge[t], pi = sgp[t];
        int cnt = 0;
        for (int j = 0; j < NN; j++) {
            unsigned dg = (unsigned)(sge[j] - gi + 1);
            unsigned dp = (unsigned)(sgp[j] - pi + 1);
            if (dg <= 2u && dp <= 2u)
                nb[t][cnt++] = (unsigned short)(j | ((dg * 3 + dp) << 8));
        }
        scnt[t] = cnt;
    } else {
        for (int i = t - 128; i < 9 * CC; i += 384) shK[i] = ck[i];
        if (t >= 256 && t < 512 && (t - 256) < 256) shB[t - 256] = cb[t - 256];
    }
    __syncthreads();

    // ---- conv -> SMEM A (bf16 hi/lo, swizzled) ----
    {
        const float* xb = x + (size_t)b * NN * CC;
        int c0 = lane * 8;
        char* achunk = smem + SA + (lane >> 2) * 16384;   // chunk = c0>>5
        uint32_t qbh = (uint32_t)(lane & 3);              // hi quad base
        uint32_t qbl = (uint32_t)(4 + (lane & 3));        // lo quad base

        #pragma unroll
        for (int s = 0; s < 8; s++) {
            int i = w * 8 + s;
            float acc[8];
            #pragma unroll
            for (int u = 0; u < 8; u++) acc[u] = shB[c0 + u];

            int cnt = scnt[i];
            for (int e = 0; e < cnt; e++) {
                int pk = nb[i][e];
                int j = pk & 0xFF;
                int kk = pk >> 8;
                const float4* xp = (const float4*)(xb + (size_t)j * CC + c0);
                float4 a0 = xp[0];
                float4 a1 = xp[1];
                const float4* kp = (const float4*)(shK + kk * CC + c0);
                float4 k0 = kp[0];
                float4 k1 = kp[1];
                acc[0] += k0.x * a0.x; acc[1] += k0.y * a0.y;
                acc[2] += k0.z * a0.z; acc[3] += k0.w * a0.w;
                acc[4] += k1.x * a1.x; acc[5] += k1.y * a1.y;
                acc[6] += k1.z * a1.z; acc[7] += k1.w * a1.w;
            }

            uint32_t hi[4], lo[4];
            split_pack(acc, hi, lo);
            char* ap = achunk + i * 128;
            uint32_t r7 = (uint32_t)(i & 7);
            *(uint4*)(ap + ((qbh ^ r7) * 16)) = make_uint4(hi[0], hi[1], hi[2], hi[3]);
            *(uint4*)(ap + ((qbl ^ r7) * 16)) = make_uint4(lo[0], lo[1], lo[2], lo[3]);
        }
    }
    __syncthreads();

    // ---- GEMM: M=128 N=256 K=256, 16 warps, warp tile 64x32 ----
    int mw = w & 1;
    int nw = w >> 1;

    float acc[4][4][4];
    #pragma unroll
    for (int i = 0; i < 4; i++)
        #pragma unroll
        for (int j = 0; j < 4; j++)
            #pragma unroll
            for (int d = 0; d < 4; d++) acc[i][j][d] = 0.f;

    int aRow = (lane & 7) + ((lane >> 3) & 1) * 8;          // + mt*16 + mw*64
    uint32_t l7 = (uint32_t)(lane & 7);
    uint32_t qk = (uint32_t)(lane >> 4);                     // 16B half within 32B
    uint32_t qhi[2], qlo[2];
    #pragma unroll
    for (int ks = 0; ks < 2; ks++) {
        qhi[ks] = (((uint32_t)(ks * 2) + qk) ^ l7) * 16;
        qlo[ks] = (((uint32_t)(4 + ks * 2) + qk) ^ l7) * 16;
    }
    uint32_t aBase = sb + SA + (mw * 64 + aRow) * 128;

    int bRow = (lane & 7) + ((lane >= 16) ? 8 : 0);
    uint32_t bKb = (uint32_t)(((lane >> 3) & 1) * 16);

    for (int kc = 0; kc < 8; kc++) {
        asm volatile("cp.async.wait_group 0;" ::: "memory");
        __syncthreads();
        if (kc < 7) {
            copy_stage((kc + 1) & 1, kc + 1);
            asm volatile("cp.async.commit_group;" ::: "memory");
        }

        uint32_t ca = aBase + kc * 16384;
        uint32_t st = sb + SB + (kc & 1) * STAGE;
        uint32_t sBhi = st + (nw * 32 + bRow) * ROWPAD + bKb;
        uint32_t sBlo = sBhi + ST_BLO;

        #pragma unroll
        for (int ks = 0; ks < 2; ks++) {
            uint32_t ahi[4][4], alo[4][4], bhi[4][2], blo[4][2];
            #pragma unroll
            for (int mt = 0; mt < 4; mt++) {
                uint32_t a = ca + mt * 2048;
                ldsm_x4(ahi[mt][0], ahi[mt][1], ahi[mt][2], ahi[mt][3], a + qhi[ks]);
                ldsm_x4(alo[mt][0], alo[mt][1], alo[mt][2], alo[mt][3], a + qlo[ks]);
            }
            #pragma unroll
            for (int np = 0; np < 2; np++) {
                uint32_t r0, r1, r2, r3;
                ldsm_x4(r0, r1, r2, r3, sBhi + np * (16 * ROWPAD) + ks * 32);
                bhi[2 * np][0] = r0; bhi[2 * np][1] = r1;
                bhi[2 * np + 1][0] = r2; bhi[2 * np + 1][1] = r3;
                ldsm_x4(r0, r1, r2, r3, sBlo + np * (16 * ROWPAD) + ks * 32);
                blo[2 * np][0] = r0; blo[2 * np][1] = r1;
                blo[2 * np + 1][0] = r2; blo[2 * np + 1][1] = r3;
            }
            #pragma unroll
            for (int mt = 0; mt < 4; mt++)
                #pragma unroll
                for (int nt = 0; nt < 4; nt++) {
                    mma16816(acc[mt][nt], ahi[mt], bhi[nt]);
                    mma16816(acc[mt][nt], alo[mt], bhi[nt]);
                    mma16816(acc[mt][nt], ahi[mt], blo[nt]);
                }
        }
    }

    // ---- epilogue: bias + LN + residual ----
    const float* s_db = (const float*)(smem + SPAR);
    const float* s_g  = (const float*)(smem + SPAR + 1024);
    const float* s_bt = (const float*)(smem + SPAR + 2048);
    float* redS = (float*)(smem + SRED);
    float* redQ = (float*)(smem + SRED + 4096);
    float2* smi = (float2*)(smem + SMI);

    int qr = lane >> 2, qc = lane & 3;
    int MW = mw * 64, NW = nw * 32;

    float S[4][2], Q[4][2];
    #pragma unroll
    for (int mt = 0; mt < 4; mt++) {
        S[mt][0] = S[mt][1] = 0.f;
        Q[mt][0] = Q[mt][1] = 0.f;
    }
    #pragma unroll
    for (int mt = 0; mt < 4; mt++)
        #pragma unroll
        for (int nt = 0; nt < 4; nt++)
            #pragma unroll
            for (int d = 0; d < 4; d++) {
                int col = NW + nt * 8 + qc * 2 + (d & 1);
                float v = acc[mt][nt][d] + s_db[col];
                acc[mt][nt][d] = v;
                S[mt][d >> 1] += v;
                Q[mt][d >> 1] += v * v;
            }
    #pragma unroll
    for (int mt = 0; mt < 4; mt++)
        #pragma unroll
        for (int h = 0; h < 2; h++) {
            #pragma unroll
            for (int off = 1; off <= 2; off <<= 1) {
                S[mt][h] += __shfl_xor_sync(0xffffffffu, S[mt][h], off);
                Q[mt][h] += __shfl_xor_sync(0xffffffffu, Q[mt][h], off);
            }
        }
    __syncthreads();   // shK (aliasing redS/redQ) no longer needed; safe to overwrite
    if (qc == 0) {
        #pragma unroll
        for (int mt = 0; mt < 4; mt++)
            #pragma unroll
            for (int h = 0; h < 2; h++) {
                int row = MW + mt * 16 + qr + h * 8;
                redS[row * 8 + nw] = S[mt][h];
                redQ[row * 8 + nw] = Q[mt][h];
            }
    }
    __syncthreads();

    if (t < 128) {
        float s = 0.f, q = 0.f;
        #pragma unroll
        for (int k = 0; k < 8; k++) {
            s += redS[t * 8 + k];
            q += redQ[t * 8 + k];
        }
        float mean = s * (1.0f / 256.0f);
        float var = fmaf(-mean, mean, q * (1.0f / 256.0f));
        smi[t] = make_float2(mean, rsqrtf(var + 1e-6f));
    }
    __syncthreads();

    #pragma unroll
    for (int mt = 0; mt < 4; mt++)
        #pragma unroll
        for (int h = 0; h < 2; h++) {
            int row = MW + mt * 16 + qr + h * 8;
            float2 mv = smi[row];
            size_t rb = ((size_t)b * NN + row) * CC;
            #pragma unroll
            for (int nt = 0; nt < 4; nt++) {
                int col = NW + nt * 8 + qc * 2;
                float2 xv = *(const float2*)(x + rb + col);
                float v0 = (acc[mt][nt][h * 2]     - mv.x) * mv.y * s_g[col]     + s_bt[col]     + xv.x;
                float v1 = (acc[mt][nt][h * 2 + 1] - mv.x) * mv.y * s_g[col + 1] + s_bt[col + 1] + xv.y;
                *(float2*)(out + rb + col) = make_float2(v0, v1);
            }
        }
}

extern "C" void kernel_launch(void* const* d_in, const int* in_sizes, int n_in,
                              void* d_out, int out_size) {
    const float* x   = (const float*)d_in[0];
    const float* eta = (const float*)d_in[1];
    const float* phi = (const float*)d_in[2];
    const float* ck  = (const float*)d_in[3];
    const float* cb  = (const float*)d_in[4];
    const float* dw  = (const float*)d_in[5];
    const float* db  = (const float*)d_in[6];
    const float* gm  = (const float*)d_in[7];
    const float* bt  = (const float*)d_in[8];
    float* out = (float*)d_out;

    cudaFuncSetAttribute(fused_kernel,
                         cudaFuncAttributeMaxDynamicSharedMemorySize, SMEMT);

    prep_w_kernel<<<32, 256>>>(dw);
    fused_kernel<<<BB, 512, SMEMT>>>(x, eta, phi, ck, cb, db, gm, bt, out);
}